// round 3
// baseline (speedup 1.0000x reference)
#include <cuda_runtime.h>
#include <cuda_bf16.h>

// Problem constants
#define B_   4
#define N_   262144          // elements per batch (2^18)
#define F_   64
#define S_   1024            // NUM_SEG
#define OUT_ 64
#define CAP  512             // bin capacity (Poisson lambda=256, >15 sigma headroom)

// ---------------- device scratch ----------------
// Zero block (one memsetAsync per call):
//   [0, 4096)       cnt_row  int [B][S]
//   [4096, 8192)    cnt_col  int [B][S]
//   [8192, 8448)    gsum     float [B][64]
__device__ __align__(256) unsigned g_zeroblk[2 * B_ * S_ + B_ * 64];
#define CNT_ROW ((int*)g_zeroblk)
#define CNT_COL (((int*)g_zeroblk) + B_ * S_)
#define GSUM    ((float*)(g_zeroblk + 2 * B_ * S_))

__device__ __align__(256) int g_bins[2 * B_ * S_ * CAP];   // 16 MB: [side][B][S][CAP]

__device__ __align__(256) float g_M[4 * F_ * OUT_];     // M_self, M_row, M_col, M_glob
__device__ __align__(256) float g_bias_const[OUT_];
__device__ __align__(256) float g_rowvec[B_ * S_ * OUT_];
__device__ __align__(256) float g_colvec[B_ * S_ * OUT_];

// ---------------- packed fp32x2 helpers (sm_103a FFMA2) ----------------
__device__ __forceinline__ unsigned long long pk2(float x) {
    unsigned long long r;
    asm("mov.b64 %0, {%1, %1};" : "=l"(r) : "f"(x));
    return r;
}
__device__ __forceinline__ void fma2(unsigned long long& d, unsigned long long a, unsigned long long b) {
    asm("fma.rn.f32x2 %0, %1, %2, %0;" : "+l"(d) : "l"(a), "l"(b));
}
__device__ __forceinline__ float2 up2(unsigned long long v) {
    float2 r;
    asm("mov.b64 {%0, %1}, %2;" : "=f"(r.x), "=f"(r.y) : "l"(v));
    return r;
}

// ---------------- K0: fold weight matrices ----------------
__global__ void prep_kernel(const float* __restrict__ Wself, const float* __restrict__ Wrow,
                            const float* __restrict__ Wcol,  const float* __restrict__ Wglob,
                            const float* __restrict__ Wout,
                            const float* __restrict__ bself, const float* __restrict__ brow,
                            const float* __restrict__ bcol,  const float* __restrict__ bglob,
                            const float* __restrict__ bout) {
    const int stride = blockDim.x * gridDim.x;
    const int tid = blockIdx.x * blockDim.x + threadIdx.x;
    for (int job = tid; job < 4 * F_ * OUT_; job += stride) {
        const int m = job >> 12;
        const int r = job & 4095;
        const int f = r >> 6, o = r & 63;
        const float* W = (m == 0) ? Wself : (m == 1) ? Wrow : (m == 2) ? Wcol : Wglob;
        float acc = 0.f;
        #pragma unroll 16
        for (int j = 0; j < 64; ++j)
            acc += W[f * 64 + j] * Wout[(m * 64 + j) * OUT_ + o];
        g_M[job] = acc;
    }
    for (int o = tid; o < OUT_; o += stride) {
        float acc = bout[o];
        for (int j = 0; j < 64; ++j) {
            acc += bself[j] * Wout[j * OUT_ + o];
            acc += brow [j] * Wout[(64  + j) * OUT_ + o];
            acc += bcol [j] * Wout[(128 + j) * OUT_ + o];
            acc += bglob[j] * Wout[(192 + j) * OUT_ + o];
        }
        g_bias_const[o] = acc;
    }
}

// ---------------- K1: binning ----------------
__global__ void __launch_bounds__(256) bin_kernel(const int* __restrict__ index) {
    const int e = blockIdx.x * 256 + threadIdx.x;
    const int b = e >> 18;
    const int local = e & (N_ - 1);
    const int2 p = ((const int2*)index)[e];
    const int r = (b << 10) + p.x;
    const int c = (b << 10) + p.y;
    int pos0 = atomicAdd(CNT_ROW + r, 1);
    if (pos0 < CAP) g_bins[r * CAP + pos0] = local;
    int pos1 = atomicAdd(CNT_COL + c, 1);
    if (pos1 < CAP) g_bins[(B_ * S_ + c) * CAP + pos1] = local;
}

// ---------------- K2: per-segment reduce + fused GEMV ----------------
// One warp per (side, b, seg). Fixed-unroll gather batches keep 8 loads in
// flight (MLP=8) so the 512MB random-row gather runs at LTS/DRAM throughput,
// not single-load latency.
__global__ void __launch_bounds__(256) reduce_kernel(const float* __restrict__ value) {
    __shared__ float Ms[2 * 4096];   // M_row then M_col
    const int tid = threadIdx.x;
    {
        const float4* src = (const float4*)(g_M + 4096);
        float4* dst = (float4*)Ms;
        #pragma unroll
        for (int i = 0; i < 8; ++i) dst[tid + i * 256] = src[tid + i * 256];
    }
    __syncthreads();

    const int warp = tid >> 5, lane = tid & 31;
    const int job = blockIdx.x * 8 + warp;            // 0 .. 8191
    const int side = job >> 12;
    const int bs = job & 4095;
    const int b = bs >> 10;

    const int cnt = (side ? CNT_COL : CNT_ROW)[bs];
    const int mn = min(cnt, CAP);
    const int* ids = g_bins + ((long long)side * B_ * S_ + bs) * CAP;
    const float* vb = value + ((long long)b << 24);

    float2 acc = make_float2(0.f, 0.f);
    int base = 0;
    for (; base + 32 <= mn; base += 32) {
        const int idv = ids[base + lane];
        #pragma unroll
        for (int jj = 0; jj < 32; jj += 8) {
            float2 v[8];
            #pragma unroll
            for (int j = 0; j < 8; ++j) {
                const int id = __shfl_sync(0xffffffff, idv, jj + j);
                v[j] = *(const float2*)(vb + ((long long)id << 6) + (lane << 1));
            }
            #pragma unroll
            for (int j = 0; j < 8; ++j) { acc.x += v[j].x; acc.y += v[j].y; }
        }
    }
    { // tail (< 32 elements)
        const int rem = mn - base;
        const int idv = (lane < rem) ? ids[base + lane] : 0;
        for (int j = 0; j < rem; ++j) {
            const int id = __shfl_sync(0xffffffff, idv, j);
            const float2 v = *(const float2*)(vb + ((long long)id << 6) + (lane << 1));
            acc.x += v.x; acc.y += v.y;
        }
    }

    if (side == 0) {   // feed global-sum path
        atomicAdd(GSUM + b * 64 + (lane << 1),     acc.x);
        atomicAdd(GSUM + b * 64 + (lane << 1) + 1, acc.y);
    }

    const float inv = 1.0f / ((float)cnt + 1e-9f);
    const float2 mean = make_float2(acc.x * inv, acc.y * inv);

    const float* M = Ms + side * 4096;
    float r0 = 0.f, r1 = 0.f;
    #pragma unroll 8
    for (int j = 0; j < 32; ++j) {
        const float m0 = __shfl_sync(0xffffffff, mean.x, j);
        const float m1 = __shfl_sync(0xffffffff, mean.y, j);
        r0 += m0 * M[(2 * j) * 64 + lane]      + m1 * M[(2 * j + 1) * 64 + lane];
        r1 += m0 * M[(2 * j) * 64 + lane + 32] + m1 * M[(2 * j + 1) * 64 + lane + 32];
    }
    float* dst = (side ? g_colvec : g_rowvec) + ((long long)bs << 6);
    dst[lane]      = r0;
    dst[lane + 32] = r1;
}

// ---------------- K3: fused GEMV + gather + bias + LReLU ----------------
// (gbias folded in: each block derives the per-batch bias from GSUM)
#define SMEM_MAIN ((128*68 + 4096 + 64)*4 + 256*4)
__global__ void __launch_bounds__(256) main_kernel(const float* __restrict__ value,
                                                   const int* __restrict__ index,
                                                   float* __restrict__ out) {
    extern __shared__ float sm[];
    float* Vs  = sm;                   // [128][68]
    float* Ms  = sm + 128 * 68;        // [64][64]
    float* bbS = Ms + 4096;            // [64]
    int*   Is  = (int*)(bbS + 64);     // [128][2]
    const int tid = threadIdx.x;
    const long long base = (long long)blockIdx.x * 128;
    const int b = (int)(base >> 18);

    {
        const float4* Mg = (const float4*)g_M;
        float4* Md = (float4*)Ms;
        #pragma unroll
        for (int i = 0; i < 4; ++i) Md[tid + i * 256] = Mg[tid + i * 256];
    }
    if (tid < 64) {   // per-batch bias: bias_const + (GSUM/N) @ M_glob
        float acc = g_bias_const[tid];
        const float s = 1.0f / (float)N_;
        #pragma unroll 8
        for (int f = 0; f < 64; ++f)
            acc += (GSUM[(b << 6) + f] * s) * g_M[3 * 4096 + f * 64 + tid];
        bbS[tid] = acc;
    }
    {
        const float4* Vg = (const float4*)(value + (base << 6));
        #pragma unroll
        for (int i = 0; i < 8; ++i) {
            const int li = tid + i * 256;
            const float4 v = Vg[li];
            const int L = li << 2;
            const int r = L >> 6, c = L & 63;
            *(float4*)(Vs + r * 68 + c) = v;
        }
    }
    if (tid < 128) {
        const int2 p = ((const int2*)index)[base + tid];
        Is[2 * tid] = p.x; Is[2 * tid + 1] = p.y;
    }
    __syncthreads();

    const int tx = tid & 7, ty = tid >> 3;
    const int o0 = tx << 3;
    const int r0 = ty << 2;

    unsigned long long acc[4][4];
    #pragma unroll
    for (int j = 0; j < 4; ++j)
        #pragma unroll
        for (int p = 0; p < 4; ++p) acc[j][p] = 0ull;

    #pragma unroll 8
    for (int k = 0; k < 64; ++k) {
        const ulonglong2 mA = *(const ulonglong2*)(Ms + k * 64 + o0);
        const ulonglong2 mB = *(const ulonglong2*)(Ms + k * 64 + o0 + 4);
        #pragma unroll
        for (int j = 0; j < 4; ++j) {
            const unsigned long long a = pk2(Vs[(r0 + j) * 68 + k]);
            fma2(acc[j][0], a, mA.x);
            fma2(acc[j][1], a, mA.y);
            fma2(acc[j][2], a, mB.x);
            fma2(acc[j][3], a, mB.y);
        }
    }

    const float4 bb0 = *(const float4*)(bbS + o0);
    const float4 bb1 = *(const float4*)(bbS + o0 + 4);
    #pragma unroll
    for (int j = 0; j < 4; ++j) {
        const int r = r0 + j;
        const int i0 = Is[2 * r], i1 = Is[2 * r + 1];
        const float* rv = g_rowvec + ((((long long)b << 10) + i0) << 6) + o0;
        const float* cv = g_colvec + ((((long long)b << 10) + i1) << 6) + o0;
        const float4 R0 = *(const float4*)rv,       R1 = *(const float4*)(rv + 4);
        const float4 C0 = *(const float4*)cv,       C1 = *(const float4*)(cv + 4);
        const float2 a0 = up2(acc[j][0]), a1 = up2(acc[j][1]);
        const float2 a2 = up2(acc[j][2]), a3 = up2(acc[j][3]);
        float o_[8] = { a0.x + R0.x + C0.x + bb0.x,
                        a0.y + R0.y + C0.y + bb0.y,
                        a1.x + R0.z + C0.z + bb0.z,
                        a1.y + R0.w + C0.w + bb0.w,
                        a2.x + R1.x + C1.x + bb1.x,
                        a2.y + R1.y + C1.y + bb1.y,
                        a3.x + R1.z + C1.z + bb1.z,
                        a3.y + R1.w + C1.w + bb1.w };
        #pragma unroll
        for (int q = 0; q < 8; ++q) o_[q] = fmaxf(o_[q], 0.01f * o_[q]);
        float* op = out + ((base + r) << 6) + o0;
        *(float4*)op       = make_float4(o_[0], o_[1], o_[2], o_[3]);
        *(float4*)(op + 4) = make_float4(o_[4], o_[5], o_[6], o_[7]);
    }
}

// ---------------- index pass-through ----------------
__global__ void idxcopy_kernel(const int* __restrict__ idx, float* __restrict__ out, int n4) {
    const int i = blockIdx.x * blockDim.x + threadIdx.x;
    if (i < n4) {
        const int4 v = ((const int4*)idx)[i];
        ((float4*)out)[i] = make_float4((float)v.x, (float)v.y, (float)v.z, (float)v.w);
    }
}

// ---------------- launch ----------------
extern "C" void kernel_launch(void* const* d_in, const int* in_sizes, int n_in,
                              void* d_out, int out_size) {
    const int*   index = (const int*)d_in[0];
    const float* value = (const float*)d_in[1];
    const float* Wself = (const float*)d_in[2];
    const float* bself = (const float*)d_in[3];
    const float* Wrow  = (const float*)d_in[4];
    const float* brow  = (const float*)d_in[5];
    const float* Wcol  = (const float*)d_in[6];
    const float* bcol  = (const float*)d_in[7];
    const float* Wglob = (const float*)d_in[8];
    const float* bglob = (const float*)d_in[9];
    const float* Wout  = (const float*)d_in[10];
    const float* bout  = (const float*)d_in[11];
    float* out = (float*)d_out;

    const long long main_elems = (long long)B_ * N_ * OUT_;
    const long long off = (long long)out_size - main_elems;
    float* out_main = (off > 0) ? (out + off) : out;

    void* zp = nullptr;
    cudaGetSymbolAddress(&zp, g_zeroblk);
    cudaMemsetAsync(zp, 0, sizeof(g_zeroblk), 0);                         // launch 1

    cudaFuncSetAttribute(main_kernel, cudaFuncAttributeMaxDynamicSharedMemorySize, SMEM_MAIN);

    prep_kernel<<<64, 256>>>(Wself, Wrow, Wcol, Wglob, Wout,
                             bself, brow, bcol, bglob, bout);             // launch 2
    bin_kernel<<<(B_ * N_) / 256, 256>>>(index);                          // launch 3
    reduce_kernel<<<1024, 256>>>(value);                                  // launch 4
    main_kernel<<<(B_ * N_) / 128, 256, SMEM_MAIN>>>(value, index, out_main); // launch 5 (profiled)

    if (off > 0) {
        const int n4 = (int)(off / 4);
        idxcopy_kernel<<<(n4 + 255) / 256, 256>>>(index, out, n4);        // launch 6
    }
}

// round 4
// speedup vs baseline: 1.0902x; 1.0902x over previous
#include <cuda_runtime.h>
#include <cuda_bf16.h>

// Problem constants
#define B_   4
#define N_   262144          // elements per batch (2^18)
#define F_   64
#define S_   1024            // NUM_SEG
#define OUT_ 64
#define CAP  512             // bin capacity (Poisson lambda=256, >15 sigma headroom)

// ---------------- device scratch ----------------
__device__ __align__(256) unsigned g_zeroblk[2 * B_ * S_ + B_ * 64];
#define CNT_ROW ((int*)g_zeroblk)
#define CNT_COL (((int*)g_zeroblk) + B_ * S_)
#define GSUM    ((float*)(g_zeroblk + 2 * B_ * S_))

__device__ __align__(256) int g_bins[2 * B_ * S_ * CAP];   // 16 MB

__device__ __align__(256) float g_M[4 * F_ * OUT_];        // M_self, M_row, M_col, M_glob
__device__ __align__(256) float g_Mint[F_ * OUT_];         // M_self k-pair interleaved: [kk][o] = (M[2kk][o], M[2kk+1][o])
__device__ __align__(256) float g_bias_const[OUT_];
__device__ __align__(256) float g_rowvec[B_ * S_ * OUT_];  // paired layout: float2[(b,s)][32] = (out o, out o+32)
__device__ __align__(256) float g_colvec[B_ * S_ * OUT_];

// ---------------- packed fp32x2 helpers (sm_103a FFMA2) ----------------
__device__ __forceinline__ void fma2(unsigned long long& d, unsigned long long a, unsigned long long b) {
    asm("fma.rn.f32x2 %0, %1, %2, %0;" : "+l"(d) : "l"(a), "l"(b));
}
__device__ __forceinline__ float2 up2(unsigned long long v) {
    float2 r;
    asm("mov.b64 {%0, %1}, %2;" : "=f"(r.x), "=f"(r.y) : "l"(v));
    return r;
}

// ---------------- K0: fold weight matrices ----------------
__global__ void prep_kernel(const float* __restrict__ Wself, const float* __restrict__ Wrow,
                            const float* __restrict__ Wcol,  const float* __restrict__ Wglob,
                            const float* __restrict__ Wout,
                            const float* __restrict__ bself, const float* __restrict__ brow,
                            const float* __restrict__ bcol,  const float* __restrict__ bglob,
                            const float* __restrict__ bout) {
    const int stride = blockDim.x * gridDim.x;
    const int tid = blockIdx.x * blockDim.x + threadIdx.x;
    for (int job = tid; job < 4 * F_ * OUT_; job += stride) {
        const int m = job >> 12;
        const int r = job & 4095;
        const int f = r >> 6, o = r & 63;
        const float* W = (m == 0) ? Wself : (m == 1) ? Wrow : (m == 2) ? Wcol : Wglob;
        float acc = 0.f;
        #pragma unroll 16
        for (int j = 0; j < 64; ++j)
            acc += W[f * 64 + j] * Wout[(m * 64 + j) * OUT_ + o];
        g_M[job] = acc;
        if (m == 0)   // k-pair interleaved copy of M_self for the main kernel
            g_Mint[(f >> 1) * 128 + o * 2 + (f & 1)] = acc;
    }
    for (int o = tid; o < OUT_; o += stride) {
        float acc = bout[o];
        for (int j = 0; j < 64; ++j) {
            acc += bself[j] * Wout[j * OUT_ + o];
            acc += brow [j] * Wout[(64  + j) * OUT_ + o];
            acc += bcol [j] * Wout[(128 + j) * OUT_ + o];
            acc += bglob[j] * Wout[(192 + j) * OUT_ + o];
        }
        g_bias_const[o] = acc;
    }
}

// ---------------- K1: binning ----------------
__global__ void __launch_bounds__(256) bin_kernel(const int* __restrict__ index) {
    const int e = blockIdx.x * 256 + threadIdx.x;
    const int b = e >> 18;
    const int local = e & (N_ - 1);
    const int2 p = ((const int2*)index)[e];
    const int r = (b << 10) + p.x;
    const int c = (b << 10) + p.y;
    int pos0 = atomicAdd(CNT_ROW + r, 1);
    if (pos0 < CAP) g_bins[r * CAP + pos0] = local;
    int pos1 = atomicAdd(CNT_COL + c, 1);
    if (pos1 < CAP) g_bins[(B_ * S_ + c) * CAP + pos1] = local;
}

// ---------------- K2: per-segment reduce + fused GEMV ----------------
__global__ void __launch_bounds__(256) reduce_kernel(const float* __restrict__ value) {
    __shared__ float Ms[2 * 4096];   // M_row then M_col
    const int tid = threadIdx.x;
    {
        const float4* src = (const float4*)(g_M + 4096);
        float4* dst = (float4*)Ms;
        #pragma unroll
        for (int i = 0; i < 8; ++i) dst[tid + i * 256] = src[tid + i * 256];
    }
    __syncthreads();

    const int warp = tid >> 5, lane = tid & 31;
    const int job = blockIdx.x * 8 + warp;            // 0 .. 8191
    const int side = job >> 12;
    const int bs = job & 4095;
    const int b = bs >> 10;

    const int cnt = (side ? CNT_COL : CNT_ROW)[bs];
    const int mn = min(cnt, CAP);
    const int* ids = g_bins + ((long long)side * B_ * S_ + bs) * CAP;
    const float* vb = value + ((long long)b << 24);

    float2 acc = make_float2(0.f, 0.f);
    int base = 0;
    for (; base + 32 <= mn; base += 32) {
        const int idv = ids[base + lane];
        #pragma unroll
        for (int jj = 0; jj < 32; jj += 8) {
            float2 v[8];
            #pragma unroll
            for (int j = 0; j < 8; ++j) {
                const int id = __shfl_sync(0xffffffff, idv, jj + j);
                v[j] = *(const float2*)(vb + ((long long)id << 6) + (lane << 1));
            }
            #pragma unroll
            for (int j = 0; j < 8; ++j) { acc.x += v[j].x; acc.y += v[j].y; }
        }
    }
    {
        const int rem = mn - base;
        const int idv = (lane < rem) ? ids[base + lane] : 0;
        for (int j = 0; j < rem; ++j) {
            const int id = __shfl_sync(0xffffffff, idv, j);
            const float2 v = *(const float2*)(vb + ((long long)id << 6) + (lane << 1));
            acc.x += v.x; acc.y += v.y;
        }
    }

    if (side == 0) {
        atomicAdd(GSUM + b * 64 + (lane << 1),     acc.x);
        atomicAdd(GSUM + b * 64 + (lane << 1) + 1, acc.y);
    }

    const float inv = 1.0f / ((float)cnt + 1e-9f);
    const float2 mean = make_float2(acc.x * inv, acc.y * inv);

    const float* M = Ms + side * 4096;
    float r0 = 0.f, r1 = 0.f;
    #pragma unroll 8
    for (int j = 0; j < 32; ++j) {
        const float m0 = __shfl_sync(0xffffffff, mean.x, j);
        const float m1 = __shfl_sync(0xffffffff, mean.y, j);
        r0 += m0 * M[(2 * j) * 64 + lane]      + m1 * M[(2 * j + 1) * 64 + lane];
        r1 += m0 * M[(2 * j) * 64 + lane + 32] + m1 * M[(2 * j + 1) * 64 + lane + 32];
    }
    // paired layout: (out lane, out lane+32)
    float2* dst = (float2*)((side ? g_colvec : g_rowvec) + ((long long)bs << 6));
    dst[lane] = make_float2(r0, r1);
}

// ---------------- K3: fused GEMV + gather + bias + LReLU ----------------
// 64 rows/block, 8 warps: warp owns 8 rows, lane owns output pair (l, l+32).
// Inner loop per k-pair: 2 lane-distinct LDS.64 (M, zero duplication) +
// 8 broadcast LDS.64 (V pairs) + 16 FFMA2 -> FMA-pipe bound, not L1.
__global__ void __launch_bounds__(256) main_kernel(const float* __restrict__ value,
                                                   const int* __restrict__ index,
                                                   float* __restrict__ out) {
    __shared__ float2 Mint[32 * 64];   // 16 KB: [kk][o] = (M[2kk][o], M[2kk+1][o])
    __shared__ float  Vs[64 * 64];     // 16 KB: 64 value rows
    __shared__ float2 bbS[32];         // per-batch bias pairs
    __shared__ int    Is[64 * 2];
    const int tid  = threadIdx.x;
    const int lane = tid & 31, warp = tid >> 5;
    const long long base = (long long)blockIdx.x * 64;
    const int b = (int)(base >> 18);

    {   // stage Mint
        const float4* src = (const float4*)g_Mint;
        float4* dst = (float4*)Mint;
        #pragma unroll
        for (int i = 0; i < 4; ++i) dst[tid + i * 256] = src[tid + i * 256];
    }
    {   // stage value rows
        const float4* Vg = (const float4*)(value + (base << 6));
        float4* Vd = (float4*)Vs;
        #pragma unroll
        for (int i = 0; i < 4; ++i) Vd[tid + i * 256] = Vg[tid + i * 256];
    }
    if (tid < 64) {
        const int2 p = ((const int2*)index)[base + tid];
        Is[2 * tid] = p.x; Is[2 * tid + 1] = p.y;
    }
    if (tid < 32) {   // per-batch bias pair: bias_const + (GSUM/N) @ M_glob
        const float s = 1.0f / (float)N_;
        float bx = g_bias_const[tid], by = g_bias_const[tid + 32];
        #pragma unroll 8
        for (int f = 0; f < 64; ++f) {
            const float gm = GSUM[(b << 6) + f] * s;
            bx += gm * g_M[3 * 4096 + f * 64 + tid];
            by += gm * g_M[3 * 4096 + f * 64 + tid + 32];
        }
        bbS[tid] = make_float2(bx, by);
    }
    __syncthreads();

    const int r0 = warp * 8;
    unsigned long long accA[8], accB[8];
    #pragma unroll
    for (int r = 0; r < 8; ++r) { accA[r] = 0ull; accB[r] = 0ull; }

    const unsigned long long* Mrow = (const unsigned long long*)Mint;
    #pragma unroll 8
    for (int kk = 0; kk < 32; ++kk) {
        const unsigned long long mlo = Mrow[kk * 64 + lane];        // (M[2kk][l],   M[2kk+1][l])
        const unsigned long long mhi = Mrow[kk * 64 + lane + 32];   // (M[2kk][l+32],M[2kk+1][l+32])
        #pragma unroll
        for (int r = 0; r < 8; ++r) {
            const unsigned long long a =
                *(const unsigned long long*)(Vs + (r0 + r) * 64 + 2 * kk);  // broadcast (V[k0],V[k1])
            fma2(accA[r], a, mlo);
            fma2(accB[r], a, mhi);
        }
    }

    const float2 bb = bbS[lane];
    #pragma unroll
    for (int r = 0; r < 8; ++r) {
        const int row = r0 + r;
        const int i0 = Is[2 * row], i1 = Is[2 * row + 1];
        const float2 rv = ((const float2*)g_rowvec)[((((long long)b << 10) + i0) << 5) + lane];
        const float2 cv = ((const float2*)g_colvec)[((((long long)b << 10) + i1) << 5) + lane];
        const float2 pa = up2(accA[r]);
        const float2 pb = up2(accB[r]);
        float x = (pa.x + pa.y) + rv.x + cv.x + bb.x;
        float y = (pb.x + pb.y) + rv.y + cv.y + bb.y;
        x = fmaxf(x, 0.01f * x);
        y = fmaxf(y, 0.01f * y);
        float* op = out + ((base + row) << 6);
        op[lane]      = x;
        op[lane + 32] = y;
    }
}

// ---------------- index pass-through ----------------
__global__ void idxcopy_kernel(const int* __restrict__ idx, float* __restrict__ out, int n4) {
    const int i = blockIdx.x * blockDim.x + threadIdx.x;
    if (i < n4) {
        const int4 v = ((const int4*)idx)[i];
        ((float4*)out)[i] = make_float4((float)v.x, (float)v.y, (float)v.z, (float)v.w);
    }
}

// ---------------- launch ----------------
extern "C" void kernel_launch(void* const* d_in, const int* in_sizes, int n_in,
                              void* d_out, int out_size) {
    const int*   index = (const int*)d_in[0];
    const float* value = (const float*)d_in[1];
    const float* Wself = (const float*)d_in[2];
    const float* bself = (const float*)d_in[3];
    const float* Wrow  = (const float*)d_in[4];
    const float* brow  = (const float*)d_in[5];
    const float* Wcol  = (const float*)d_in[6];
    const float* bcol  = (const float*)d_in[7];
    const float* Wglob = (const float*)d_in[8];
    const float* bglob = (const float*)d_in[9];
    const float* Wout  = (const float*)d_in[10];
    const float* bout  = (const float*)d_in[11];
    float* out = (float*)d_out;

    const long long main_elems = (long long)B_ * N_ * OUT_;
    const long long off = (long long)out_size - main_elems;
    float* out_main = (off > 0) ? (out + off) : out;

    void* zp = nullptr;
    cudaGetSymbolAddress(&zp, g_zeroblk);
    cudaMemsetAsync(zp, 0, sizeof(g_zeroblk), 0);

    prep_kernel<<<64, 256>>>(Wself, Wrow, Wcol, Wglob, Wout,
                             bself, brow, bcol, bglob, bout);             // kernel 1
    bin_kernel<<<(B_ * N_) / 256, 256>>>(index);                          // kernel 2
    if (off > 0) {
        const int n4 = (int)(off / 4);
        idxcopy_kernel<<<(n4 + 255) / 256, 256>>>(index, out, n4);        // kernel 3
    }
    reduce_kernel<<<1024, 256>>>(value);                                  // kernel 4 (profiled)
    main_kernel<<<(B_ * N_) / 64, 256>>>(value, index, out_main);         // kernel 5
}

// round 5
// speedup vs baseline: 1.2961x; 1.1889x over previous
#include <cuda_runtime.h>
#include <cuda_bf16.h>

// Problem constants
#define B_   4
#define N_   262144          // elements per batch (2^18)
#define F_   64
#define S_   1024            // NUM_SEG
#define OUT_ 64
#define CAP  512             // bin capacity (Poisson lambda=256, >15 sigma headroom)

// ---------------- device scratch ----------------
__device__ __align__(256) unsigned g_zeroblk[2 * B_ * S_ + B_ * 64];
#define CNT_ROW ((int*)g_zeroblk)
#define CNT_COL (((int*)g_zeroblk) + B_ * S_)
#define GSUM    ((float*)(g_zeroblk + 2 * B_ * S_))

__device__ __align__(256) int g_bins[2 * B_ * S_ * CAP];   // 16 MB

__device__ __align__(256) float g_M[4 * F_ * OUT_];        // M_self, M_row, M_col, M_glob
__device__ __align__(256) float g_Mint[F_ * OUT_];         // M_self k-pair interleaved
__device__ __align__(256) float g_bias_const[OUT_];
__device__ __align__(256) float g_rowvec[B_ * S_ * OUT_];  // paired: float2[(b,s)][32] = (o, o+32)
__device__ __align__(256) float g_colvec[B_ * S_ * OUT_];

// ---------------- packed fp32x2 helpers (sm_103a FFMA2) ----------------
__device__ __forceinline__ void fma2(unsigned long long& d, unsigned long long a, unsigned long long b) {
    asm("fma.rn.f32x2 %0, %1, %2, %0;" : "+l"(d) : "l"(a), "l"(b));
}
__device__ __forceinline__ float2 up2(unsigned long long v) {
    float2 r;
    asm("mov.b64 {%0, %1}, %2;" : "=f"(r.x), "=f"(r.y) : "l"(v));
    return r;
}

// ---------------- K0: fold weight matrices ----------------
__global__ void prep_kernel(const float* __restrict__ Wself, const float* __restrict__ Wrow,
                            const float* __restrict__ Wcol,  const float* __restrict__ Wglob,
                            const float* __restrict__ Wout,
                            const float* __restrict__ bself, const float* __restrict__ brow,
                            const float* __restrict__ bcol,  const float* __restrict__ bglob,
                            const float* __restrict__ bout) {
    const int stride = blockDim.x * gridDim.x;
    const int tid = blockIdx.x * blockDim.x + threadIdx.x;
    for (int job = tid; job < 4 * F_ * OUT_; job += stride) {
        const int m = job >> 12;
        const int r = job & 4095;
        const int f = r >> 6, o = r & 63;
        const float* W = (m == 0) ? Wself : (m == 1) ? Wrow : (m == 2) ? Wcol : Wglob;
        float acc = 0.f;
        #pragma unroll 16
        for (int j = 0; j < 64; ++j)
            acc += W[f * 64 + j] * Wout[(m * 64 + j) * OUT_ + o];
        g_M[job] = acc;
        if (m == 0)
            g_Mint[(f >> 1) * 128 + o * 2 + (f & 1)] = acc;
    }
    for (int o = tid; o < OUT_; o += stride) {
        float acc = bout[o];
        for (int j = 0; j < 64; ++j) {
            acc += bself[j] * Wout[j * OUT_ + o];
            acc += brow [j] * Wout[(64  + j) * OUT_ + o];
            acc += bcol [j] * Wout[(128 + j) * OUT_ + o];
            acc += bglob[j] * Wout[(192 + j) * OUT_ + o];
        }
        g_bias_const[o] = acc;
    }
}

// ---------------- K1: block-aggregated binning ----------------
// 256 blocks x 4096 elements. Smem-count first (spread ATOMS), then ONE global
// atomic per used segment per block (8x fewer global atomics, 8x less
// same-address contention), then scatter element ids into claimed ranges.
__global__ void __launch_bounds__(256) bin_kernel(const int* __restrict__ index) {
    __shared__ int cnt[2048];     // [0,1024) row counts, [1024,2048) col counts
    __shared__ int basep[2048];
    const int tid = threadIdx.x;
    const int b = blockIdx.x >> 6;                       // 64 blocks per batch
    const long long ebase = (long long)blockIdx.x * 4096;

    #pragma unroll
    for (int i = 0; i < 8; ++i) cnt[tid + i * 256] = 0;
    __syncthreads();

    int2 p[16];
    int posr[16], posc[16];
    #pragma unroll
    for (int j = 0; j < 16; ++j) {
        p[j] = ((const int2*)index)[ebase + j * 256 + tid];
        posr[j] = atomicAdd(&cnt[p[j].x], 1);
        posc[j] = atomicAdd(&cnt[1024 + p[j].y], 1);
    }
    __syncthreads();

    for (int s = tid; s < 2048; s += 256) {
        const int c = cnt[s];
        if (c > 0) {
            int* ctr = (s < 1024) ? (CNT_ROW + (b << 10) + s)
                                  : (CNT_COL + (b << 10) + (s - 1024));
            basep[s] = atomicAdd(ctr, c);
        }
    }
    __syncthreads();

    #pragma unroll
    for (int j = 0; j < 16; ++j) {
        const int local = (int)((ebase + j * 256 + tid) & (N_ - 1));
        const int sr = basep[p[j].x] + posr[j];
        if (sr < CAP) g_bins[((b << 10) + p[j].x) * CAP + sr] = local;
        const int sc = basep[1024 + p[j].y] + posc[j];
        if (sc < CAP) g_bins[(B_ * S_ + (b << 10) + p[j].y) * CAP + sc] = local;
    }
}

// ---------------- K2: per-segment reduce + fused GEMV ----------------
__global__ void __launch_bounds__(256) reduce_kernel(const float* __restrict__ value) {
    __shared__ float Ms[2 * 4096];   // M_row then M_col
    const int tid = threadIdx.x;
    {
        const float4* src = (const float4*)(g_M + 4096);
        float4* dst = (float4*)Ms;
        #pragma unroll
        for (int i = 0; i < 8; ++i) dst[tid + i * 256] = src[tid + i * 256];
    }
    __syncthreads();

    const int warp = tid >> 5, lane = tid & 31;
    const int job = blockIdx.x * 8 + warp;            // 0 .. 8191
    const int side = job >> 12;
    const int bs = job & 4095;
    const int b = bs >> 10;

    const int cnt = (side ? CNT_COL : CNT_ROW)[bs];
    const int mn = min(cnt, CAP);
    const int* ids = g_bins + ((long long)side * B_ * S_ + bs) * CAP;
    const float* vb = value + ((long long)b << 24);

    float2 acc = make_float2(0.f, 0.f);
    int base = 0;
    for (; base + 32 <= mn; base += 32) {
        const int idv = ids[base + lane];
        #pragma unroll
        for (int jj = 0; jj < 32; jj += 16) {       // 16 loads in flight (MLP=16)
            float2 v[16];
            #pragma unroll
            for (int j = 0; j < 16; ++j) {
                const int id = __shfl_sync(0xffffffff, idv, jj + j);
                v[j] = *(const float2*)(vb + ((long long)id << 6) + (lane << 1));
            }
            #pragma unroll
            for (int j = 0; j < 16; ++j) { acc.x += v[j].x; acc.y += v[j].y; }
        }
    }
    {
        const int rem = mn - base;
        const int idv = (lane < rem) ? ids[base + lane] : 0;
        for (int j = 0; j < rem; ++j) {
            const int id = __shfl_sync(0xffffffff, idv, j);
            const float2 v = *(const float2*)(vb + ((long long)id << 6) + (lane << 1));
            acc.x += v.x; acc.y += v.y;
        }
    }

    if (side == 0) {
        atomicAdd(GSUM + b * 64 + (lane << 1),     acc.x);
        atomicAdd(GSUM + b * 64 + (lane << 1) + 1, acc.y);
    }

    const float inv = 1.0f / ((float)cnt + 1e-9f);
    const float2 mean = make_float2(acc.x * inv, acc.y * inv);

    const float* M = Ms + side * 4096;
    float r0 = 0.f, r1 = 0.f;
    #pragma unroll 8
    for (int j = 0; j < 32; ++j) {
        const float m0 = __shfl_sync(0xffffffff, mean.x, j);
        const float m1 = __shfl_sync(0xffffffff, mean.y, j);
        r0 += m0 * M[(2 * j) * 64 + lane]      + m1 * M[(2 * j + 1) * 64 + lane];
        r1 += m0 * M[(2 * j) * 64 + lane + 32] + m1 * M[(2 * j + 1) * 64 + lane + 32];
    }
    float2* dst = (float2*)((side ? g_colvec : g_rowvec) + ((long long)bs << 6));
    dst[lane] = make_float2(r0, r1);
}

// ---------------- K3: fused GEMV + gather + bias + LReLU ----------------
__global__ void __launch_bounds__(256) main_kernel(const float* __restrict__ value,
                                                   const int* __restrict__ index,
                                                   float* __restrict__ out) {
    __shared__ float2 Mint[32 * 64];   // [kk][o] = (M[2kk][o], M[2kk+1][o])
    __shared__ float  Vs[64 * 64];
    __shared__ float2 bbS[32];
    __shared__ int    Is[64 * 2];
    const int tid  = threadIdx.x;
    const int lane = tid & 31, warp = tid >> 5;
    const long long base = (long long)blockIdx.x * 64;
    const int b = (int)(base >> 18);

    {
        const float4* src = (const float4*)g_Mint;
        float4* dst = (float4*)Mint;
        #pragma unroll
        for (int i = 0; i < 4; ++i) dst[tid + i * 256] = src[tid + i * 256];
    }
    {
        const float4* Vg = (const float4*)(value + (base << 6));
        float4* Vd = (float4*)Vs;
        #pragma unroll
        for (int i = 0; i < 4; ++i) Vd[tid + i * 256] = Vg[tid + i * 256];
    }
    if (tid < 64) {
        const int2 p = ((const int2*)index)[base + tid];
        Is[2 * tid] = p.x; Is[2 * tid + 1] = p.y;
    }
    if (tid < 32) {
        const float s = 1.0f / (float)N_;
        float bx = g_bias_const[tid], by = g_bias_const[tid + 32];
        #pragma unroll 8
        for (int f = 0; f < 64; ++f) {
            const float gm = GSUM[(b << 6) + f] * s;
            bx += gm * g_M[3 * 4096 + f * 64 + tid];
            by += gm * g_M[3 * 4096 + f * 64 + tid + 32];
        }
        bbS[tid] = make_float2(bx, by);
    }
    __syncthreads();

    const int r0 = warp * 8;
    unsigned long long accA[8], accB[8];
    #pragma unroll
    for (int r = 0; r < 8; ++r) { accA[r] = 0ull; accB[r] = 0ull; }

    const unsigned long long* Mrow = (const unsigned long long*)Mint;
    #pragma unroll 8
    for (int kk = 0; kk < 32; ++kk) {
        const unsigned long long mlo = Mrow[kk * 64 + lane];
        const unsigned long long mhi = Mrow[kk * 64 + lane + 32];
        #pragma unroll
        for (int r = 0; r < 8; ++r) {
            const unsigned long long a =
                *(const unsigned long long*)(Vs + (r0 + r) * 64 + 2 * kk);
            fma2(accA[r], a, mlo);
            fma2(accB[r], a, mhi);
        }
    }

    const float2 bb = bbS[lane];
    #pragma unroll
    for (int r = 0; r < 8; ++r) {
        const int row = r0 + r;
        const int i0 = Is[2 * row], i1 = Is[2 * row + 1];
        const float2 rv = ((const float2*)g_rowvec)[((((long long)b << 10) + i0) << 5) + lane];
        const float2 cv = ((const float2*)g_colvec)[((((long long)b << 10) + i1) << 5) + lane];
        const float2 pa = up2(accA[r]);
        const float2 pb = up2(accB[r]);
        float x = (pa.x + pa.y) + rv.x + cv.x + bb.x;
        float y = (pb.x + pb.y) + rv.y + cv.y + bb.y;
        x = fmaxf(x, 0.01f * x);
        y = fmaxf(y, 0.01f * y);
        float* op = out + ((base + row) << 6);
        op[lane]      = x;
        op[lane + 32] = y;
    }
}

// ---------------- index pass-through ----------------
__global__ void idxcopy_kernel(const int* __restrict__ idx, float* __restrict__ out, int n4) {
    const int i = blockIdx.x * blockDim.x + threadIdx.x;
    if (i < n4) {
        const int4 v = ((const int4*)idx)[i];
        ((float4*)out)[i] = make_float4((float)v.x, (float)v.y, (float)v.z, (float)v.w);
    }
}

// ---------------- launch ----------------
extern "C" void kernel_launch(void* const* d_in, const int* in_sizes, int n_in,
                              void* d_out, int out_size) {
    const int*   index = (const int*)d_in[0];
    const float* value = (const float*)d_in[1];
    const float* Wself = (const float*)d_in[2];
    const float* bself = (const float*)d_in[3];
    const float* Wrow  = (const float*)d_in[4];
    const float* brow  = (const float*)d_in[5];
    const float* Wcol  = (const float*)d_in[6];
    const float* bcol  = (const float*)d_in[7];
    const float* Wglob = (const float*)d_in[8];
    const float* bglob = (const float*)d_in[9];
    const float* Wout  = (const float*)d_in[10];
    const float* bout  = (const float*)d_in[11];
    float* out = (float*)d_out;

    const long long main_elems = (long long)B_ * N_ * OUT_;
    const long long off = (long long)out_size - main_elems;
    float* out_main = (off > 0) ? (out + off) : out;

    void* zp = nullptr;
    cudaGetSymbolAddress(&zp, g_zeroblk);
    cudaMemsetAsync(zp, 0, sizeof(g_zeroblk), 0);

    prep_kernel<<<64, 256>>>(Wself, Wrow, Wcol, Wglob, Wout,
                             bself, brow, bcol, bglob, bout);                 // kernel 1
    bin_kernel<<<(B_ * N_) / 4096, 256>>>(index);                             // kernel 2
    reduce_kernel<<<1024, 256>>>(value);                                      // kernel 3
    main_kernel<<<(B_ * N_) / 64, 256>>>(value, index, out_main);             // kernel 4 (profiled)
    if (off > 0) {
        const int n4 = (int)(off / 4);
        idxcopy_kernel<<<(n4 + 255) / 256, 256>>>(index, out, n4);            // kernel 5
    }
}